// round 13
// baseline (speedup 1.0000x reference)
#include <cuda_runtime.h>
#include <math.h>
#include <stdint.h>

#define HIDDEN   256
#define HEADS    8
#define HEAD_DIM 32
#define NGRAPH   16
#define MAXN     4096
#define LN_EPS   1e-5f
#define ATT_SCALE 0.17677669529663687f  /* 32^-0.5 */

// ---------------- device scratch (no allocation allowed) ----------------
// g_h, g_q, g_k, g_v hold tf32 BIT PATTERNS stored as float.
// g_k rows are PAIR-PERMUTED within each 8-col block: col c -> 2*(c&3)+(c>>2).
// g_att0/g_att1 hold fp32 UNNORMALIZED partial attention outputs (key halves).
__device__ float    g_h   [MAXN * HIDDEN];
__device__ float    g_q   [MAXN * HIDDEN];
__device__ float    g_k   [MAXN * HIDDEN];
__device__ float    g_v   [MAXN * HIDDEN];
__device__ float    g_att0[MAXN * HIDDEN];
__device__ float    g_att1[MAXN * HIDDEN];
__device__ float    g_l0  [MAXN * HEADS];
__device__ float    g_l1  [MAXN * HEADS];
__device__ uint32_t g_w4  [4 * HIDDEN * HIDDEN];   // Wq,Wk,Wv,Wo pre-converted tf32
__device__ int      g_batch[MAXN];
__device__ int      g_gstart[NGRAPH + 1];

// ---------------------------------------------------------------------------
// tf32 + cp.async helpers
// ---------------------------------------------------------------------------
__device__ __forceinline__ uint32_t f2tf(float f) {
    uint32_t r;
    asm("cvt.rna.tf32.f32 %0, %1;" : "=r"(r) : "f"(f));
    return r;
}

__device__ __forceinline__ void mma_tf32(float* c, const uint32_t* a, const uint32_t* b) {
    asm volatile(
        "mma.sync.aligned.m16n8k8.row.col.f32.tf32.tf32.f32 "
        "{%0,%1,%2,%3}, {%4,%5,%6,%7}, {%8,%9}, {%0,%1,%2,%3};"
        : "+f"(c[0]), "+f"(c[1]), "+f"(c[2]), "+f"(c[3])
        : "r"(a[0]), "r"(a[1]), "r"(a[2]), "r"(a[3]), "r"(b[0]), "r"(b[1]));
}

__device__ __forceinline__ void cp_async16(uint32_t dst, const void* src, int srcsz) {
    asm volatile("cp.async.cg.shared.global [%0], [%1], 16, %2;"
                 :: "r"(dst), "l"(src), "r"(srcsz));
}
__device__ __forceinline__ void cp_commit() { asm volatile("cp.async.commit_group;"); }
__device__ __forceinline__ void cp_wait1()  { asm volatile("cp.async.wait_group 1;"); }
__device__ __forceinline__ void cp_wait0()  { asm volatile("cp.async.wait_group 0;"); }

// ---------------------------------------------------------------------------
// Kernel 1: prep. Block 0: batch dtype probe + segment offsets.
// Blocks 1..64: convert the 4 weight matrices to tf32 bits in g_w4.
// ---------------------------------------------------------------------------
__global__ void prep_kernel(const int* __restrict__ raw, int n,
                            const float* __restrict__ Wq, const float* __restrict__ Wk,
                            const float* __restrict__ Wv, const float* __restrict__ Wo) {
    int tid = threadIdx.x;
    if (blockIdx.x == 0) {
        __shared__ int s_odd, s_even;
        __shared__ int s_cnt[NGRAPH];
        if (tid == 0) { s_odd = 0; s_even = 0; }
        if (tid < NGRAPH) s_cnt[tid] = 0;
        __syncthreads();

        int odd = 0, even = 0;
        for (int i = tid; i < n; i += blockDim.x) {
            int v = raw[i];
            if (v != 0) { if (i & 1) odd = 1; else even = 1; }
        }
        if (odd)  atomicOr(&s_odd, 1);
        if (even) atomicOr(&s_even, 1);
        __syncthreads();

        bool is64 = (s_odd == 0) && (s_even != 0);
        for (int i = tid; i < n; i += blockDim.x) {
            int v = is64 ? raw[2 * i] : raw[i];
            v = min(max(v, 0), NGRAPH - 1);
            g_batch[i] = v;
            atomicAdd(&s_cnt[v], 1);
        }
        __syncthreads();
        if (tid == 0) {
            int acc = 0;
            for (int g = 0; g < NGRAPH; g++) { g_gstart[g] = acc; acc += s_cnt[g]; }
            g_gstart[NGRAPH] = acc;
        }
    } else {
        int blk = blockIdx.x - 1;
        #pragma unroll
        for (int it = 0; it < 4; it++) {
            int e4 = blk * 1024 + it * 256 + tid;
            int m = e4 >> 14;
            int off4 = e4 & 16383;
            const float4* src = (const float4*)(m == 0 ? Wq : m == 1 ? Wk : m == 2 ? Wv : Wo);
            float4 v = src[off4];
            uint4 w = make_uint4(f2tf(v.x), f2tf(v.y), f2tf(v.z), f2tf(v.w));
            *(uint4*)&g_w4[m * 65536 + off4 * 4] = w;
        }
    }
}

// ---------------------------------------------------------------------------
// Kernel 2: LayerNorm, writes tf32 bits. One block per row, 256 threads.
// ---------------------------------------------------------------------------
__global__ void ln_kernel(const float* __restrict__ x,
                          const float* __restrict__ gamma,
                          const float* __restrict__ beta,
                          float* __restrict__ h) {
    int row = blockIdx.x;
    int tid = threadIdx.x;
    float v = x[row * HIDDEN + tid];

    __shared__ float s1[8], s2[8];
    __shared__ float s_mu, s_rstd;
    float a = v, b = v * v;
    #pragma unroll
    for (int o = 16; o > 0; o >>= 1) {
        a += __shfl_xor_sync(0xffffffffu, a, o);
        b += __shfl_xor_sync(0xffffffffu, b, o);
    }
    if ((tid & 31) == 0) { s1[tid >> 5] = a; s2[tid >> 5] = b; }
    __syncthreads();
    if (tid == 0) {
        float sa = 0.f, sb = 0.f;
        #pragma unroll
        for (int i = 0; i < 8; i++) { sa += s1[i]; sb += s2[i]; }
        float mu  = sa * (1.0f / HIDDEN);
        float var = sb * (1.0f / HIDDEN) - mu * mu;
        s_mu = mu;
        s_rstd = rsqrtf(var + LN_EPS);
    }
    __syncthreads();
    float r = (v - s_mu) * s_rstd * gamma[tid] + beta[tid];
    h[row * HIDDEN + tid] = __uint_as_float(f2tf(r));
}

// ---------------------------------------------------------------------------
// tf32 GEMM core, double-buffered: C = (A @ W + bias) * oscale (+ residual).
// Block tile 64x64, BK=32, 128 threads = 4 warps (2x2), warp 32x32.
// NORM  : A := (A0 + A1) * 1/(l0+l1) per (row, head=k0>>5) — split-K combine.
// PAIRK : C written tf32 with per-8-col pair permutation (for attn K smem).
// ---------------------------------------------------------------------------
template <bool RES, bool TF32OUT, bool NORM, bool PAIRK>
__device__ __forceinline__ void gemm_core(const float* __restrict__ A0f,
                                          const float* __restrict__ A1f,
                                          const float* __restrict__ l0p,
                                          const float* __restrict__ l1p,
                                          const uint32_t* __restrict__ W,
                                          const float* __restrict__ bias,
                                          const float* __restrict__ res,
                                          float* __restrict__ C, float oscale) {
    __shared__ uint32_t As[2][64 * 32];   // swizzled
    __shared__ uint32_t Bs[2][32 * 72];   // padded stride 72

    const int tid  = threadIdx.x;
    const int lane = tid & 31;
    const int wid  = tid >> 5;
    const int wm   = wid & 1;
    const int wn   = wid >> 1;
    const int bm   = blockIdx.y * 64;
    const int bn   = blockIdx.x * 64;

    const int ar  = tid >> 1;
    const int ach = tid & 1;
    const int bk  = tid >> 4;
    const int bn4 = tid & 15;

    const int g   = lane >> 2;
    const int t   = lane & 3;
    const int swz = g << 2;

    const int arow = bm + ar;

    float acc[2][4][4] = {};

    auto load_a = [&](int k0, uint4* av) {
        if (NORM) {
            int head = k0 >> 5;
            float ls = l0p[arow * HEADS + head] + l1p[arow * HEADS + head];
            float li = (ls > 0.f) ? __frcp_rn(ls) : 0.f;
            const float4* Ap0 = (const float4*)&A0f[arow * HIDDEN + k0];
            const float4* Ap1 = (const float4*)&A1f[arow * HIDDEN + k0];
            #pragma unroll
            for (int i = 0; i < 4; i++) {
                float4 a = Ap0[ach * 4 + i];
                float4 b = Ap1[ach * 4 + i];
                av[i] = make_uint4(f2tf((a.x + b.x) * li), f2tf((a.y + b.y) * li),
                                   f2tf((a.z + b.z) * li), f2tf((a.w + b.w) * li));
            }
        } else {
            const uint4* Ap = (const uint4*)&A0f[arow * HIDDEN + k0];
            #pragma unroll
            for (int i = 0; i < 4; i++) av[i] = Ap[ach * 4 + i];
        }
    };

    uint4 av[4], bv[4];
    load_a(0, av);
    #pragma unroll
    for (int i = 0; i < 4; i++)
        bv[i] = *(const uint4*)&W[(bk + i * 8) * HIDDEN + bn + bn4 * 4];

    int buf = 0;
    for (int k0 = 0; k0 < HIDDEN; k0 += 32) {
        #pragma unroll
        for (int i = 0; i < 4; i++) {
            int c4 = ach * 4 + i;
            int phys = ar * 8 + (c4 ^ (ar & 7));
            *(uint4*)&As[buf][phys * 4] = av[i];
        }
        #pragma unroll
        for (int i = 0; i < 4; i++)
            *(uint4*)&Bs[buf][(bk + i * 8) * 72 + bn4 * 4] = bv[i];

        if (k0 + 32 < HIDDEN) {
            load_a(k0 + 32, av);
            #pragma unroll
            for (int i = 0; i < 4; i++)
                bv[i] = *(const uint4*)&W[(k0 + 32 + bk + i * 8) * HIDDEN + bn + bn4 * 4];
        }
        __syncthreads();

        #pragma unroll
        for (int kk = 0; kk < 4; kk++) {
            uint32_t afr[2][4];
            #pragma unroll
            for (int fm = 0; fm < 2; fm++) {
                int r0 = wm * 32 + fm * 16 + g;
                int r1 = r0 + 8;
                int c0 = kk * 8 + t;
                int c1 = c0 + 4;
                afr[fm][0] = As[buf][r0 * 32 + (c0 ^ swz)];
                afr[fm][1] = As[buf][r1 * 32 + (c0 ^ swz)];
                afr[fm][2] = As[buf][r0 * 32 + (c1 ^ swz)];
                afr[fm][3] = As[buf][r1 * 32 + (c1 ^ swz)];
            }
            uint32_t bfr[4][2];
            #pragma unroll
            for (int fn = 0; fn < 4; fn++) {
                int n  = wn * 32 + fn * 8 + g;
                int kb = kk * 8 + t;
                bfr[fn][0] = Bs[buf][kb * 72 + n];
                bfr[fn][1] = Bs[buf][(kb + 4) * 72 + n];
            }
            #pragma unroll
            for (int fm = 0; fm < 2; fm++)
                #pragma unroll
                for (int fn = 0; fn < 4; fn++)
                    mma_tf32(acc[fm][fn], afr[fm], bfr[fn]);
        }
        buf ^= 1;
    }

    #pragma unroll
    for (int fm = 0; fm < 2; fm++) {
        int row0 = bm + wm * 32 + fm * 16 + g;
        int row1 = row0 + 8;
        #pragma unroll
        for (int fn = 0; fn < 4; fn++) {
            int col = bn + wn * 32 + fn * 8 + t * 2;
            float2 bb = *(const float2*)&bias[col];
            float2 c0 = make_float2((acc[fm][fn][0] + bb.x) * oscale,
                                    (acc[fm][fn][1] + bb.y) * oscale);
            float2 c1 = make_float2((acc[fm][fn][2] + bb.x) * oscale,
                                    (acc[fm][fn][3] + bb.y) * oscale);
            if (PAIRK) {
                // pair-permute within the 8-col block: c -> 2*(c&3) + (c>>2)
                int base = col & ~7;
                int i0 = col & 7, i1 = i0 + 1;
                int p0 = (i0 & 4) ? (((i0 & 3) << 1) | 1) : (i0 << 1);
                int p1 = (i1 & 4) ? (((i1 & 3) << 1) | 1) : (i1 << 1);
                C[row0 * HIDDEN + base + p0] = __uint_as_float(f2tf(c0.x));
                C[row0 * HIDDEN + base + p1] = __uint_as_float(f2tf(c0.y));
                C[row1 * HIDDEN + base + p0] = __uint_as_float(f2tf(c1.x));
                C[row1 * HIDDEN + base + p1] = __uint_as_float(f2tf(c1.y));
            } else {
                if (RES) {
                    float2 r0 = *(const float2*)&res[row0 * HIDDEN + col];
                    float2 r1 = *(const float2*)&res[row1 * HIDDEN + col];
                    c0.x += r0.x; c0.y += r0.y;
                    c1.x += r1.x; c1.y += r1.y;
                }
                if (TF32OUT) {
                    c0.x = __uint_as_float(f2tf(c0.x)); c0.y = __uint_as_float(f2tf(c0.y));
                    c1.x = __uint_as_float(f2tf(c1.x)); c1.y = __uint_as_float(f2tf(c1.y));
                }
                *(float2*)&C[row0 * HIDDEN + col] = c0;
                *(float2*)&C[row1 * HIDDEN + col] = c1;
            }
        }
    }
}

__global__ void __launch_bounds__(128)
gemm_qkv_kernel(const float* __restrict__ A,
                const float* __restrict__ bq, float* __restrict__ Cq,
                const float* __restrict__ bk, float* __restrict__ Ck,
                const float* __restrict__ bv, float* __restrict__ Cv) {
    if (blockIdx.z == 0)
        gemm_core<false, true, false, false>(A, nullptr, nullptr, nullptr,
                                             g_w4, bq, nullptr, Cq, ATT_SCALE);
    else if (blockIdx.z == 1)
        gemm_core<false, true, false, true>(A, nullptr, nullptr, nullptr,
                                            g_w4 + 65536, bk, nullptr, Ck, 1.0f);
    else
        gemm_core<false, true, false, false>(A, nullptr, nullptr, nullptr,
                                             g_w4 + 2 * 65536, bv, nullptr, Cv, 1.0f);
}

__global__ void __launch_bounds__(128)
gemm_o_kernel(const float* __restrict__ bias, const float* __restrict__ res,
              float* __restrict__ C) {
    gemm_core<true, false, true, false>(g_att0, g_att1, g_l0, g_l1,
                                        g_w4 + 3 * 65536, bias, res, C, 1.0f);
}

// ---------------------------------------------------------------------------
// Kernel 4: split-K tensor-core attention, no running max (scores O(1)).
// grid = (NGRAPH, HEADS, 8): z>>1 = query quarter, z&1 = key half.
// K/V tiles loaded via cp.async (no register staging): 2-stage ring, issue
// tile tt+2 after the compute-complete barrier. g_k is pre-pair-permuted so
// K smem supports conflict-free LDS.64 B-fragments directly.
// K smem: stride 40 floats (uint2 reads, conflict-free).
// V smem: stride 40 floats (LDS.32, bank = 8*tq+gq bijective).
// ---------------------------------------------------------------------------
__global__ void __launch_bounds__(128)
attn_kernel() {
    __shared__ uint32_t Kp[2][32 * 40];
    __shared__ uint32_t Vs[2][32 * 40];
    __shared__ uint32_t Pw[4][16 * 40];

    const int gb = blockIdx.x, hh = blockIdx.y;
    const int half = blockIdx.z & 1, qz = blockIdx.z >> 1;
    const int start = g_gstart[gb], end = g_gstart[gb + 1];
    const int n = end - start;
    const int tid = threadIdx.x, lane = tid & 31, wid = tid >> 5;
    const int gq = lane >> 2, tq = lane & 3;
    const uint32_t* Q = (const uint32_t*)g_q;
    const float* K = g_k;
    const float* V = g_v;
    float* OA = half ? g_att1 : g_att0;
    float* LA = half ? g_l1   : g_l0;

    const int T = (n + 31) >> 5;
    const int tb = half ? (T >> 1) : 0;
    const int te = half ? T : (T >> 1);

    const int lj = tid >> 2;
    const int lb = tid & 3;
    const int kvoff = hh * HEAD_DIM + lb * 8;

    const uint32_t kdst0 = (uint32_t)__cvta_generic_to_shared(&Kp[0][lj * 40 + lb * 8]);
    const uint32_t kdst1 = (uint32_t)__cvta_generic_to_shared(&Kp[1][lj * 40 + lb * 8]);
    const uint32_t vdst0 = (uint32_t)__cvta_generic_to_shared(&Vs[0][lj * 40 + lb * 8]);
    const uint32_t vdst1 = (uint32_t)__cvta_generic_to_shared(&Vs[1][lj * 40 + lb * 8]);

    auto issue_tile = [&](int tt, int b) {
        int row = start + tt * 32 + lj;
        int sz = (row < end) ? 16 : 0;
        int ra = (row < end) ? row : start;           // clamp address, sz gates data
        const float* gk = &K[ra * HIDDEN + kvoff];
        const float* gv = &V[ra * HIDDEN + kvoff];
        uint32_t kd = b ? kdst1 : kdst0;
        uint32_t vd = b ? vdst1 : vdst0;
        cp_async16(kd,      gk,     sz);
        cp_async16(kd + 16, gk + 4, sz);
        cp_async16(vd,      gv,     sz);
        cp_async16(vd + 16, gv + 4, sz);
        cp_commit();
    };

    for (int qt = qz * 64; qt < n; qt += 256) {
        const int r0 = start + qt + wid * 16 + gq, r1 = r0 + 8;
        const bool v0 = r0 < end, v1 = r1 < end;

        uint32_t qa[4][4];
        #pragma unroll
        for (int kk = 0; kk < 4; kk++) {
            int c = hh * HEAD_DIM + kk * 8 + tq;
            qa[kk][0] = v0 ? Q[r0 * HIDDEN + c]     : 0u;
            qa[kk][1] = v1 ? Q[r1 * HIDDEN + c]     : 0u;
            qa[kk][2] = v0 ? Q[r0 * HIDDEN + c + 4] : 0u;
            qa[kk][3] = v1 ? Q[r1 * HIDDEN + c + 4] : 0u;
        }

        float o[4][4] = {};
        float l0 = 0.f, l1 = 0.f;

        const int nt = te - tb;
        if (nt > 0) issue_tile(tb, 0);
        if (nt > 1) issue_tile(tb + 1, 1);

        int buf = 0;
        for (int tt = tb; tt < te; tt++) {
            if (tt + 1 < te) cp_wait1(); else cp_wait0();
            __syncthreads();

            const int t0 = start + tt * 32;

            // ---- S = Q K^T (Q pre-scaled by ATT_SCALE; K pair-permuted) ----
            float s[4][4] = {};
            #pragma unroll
            for (int fn = 0; fn < 4; fn++) {
                #pragma unroll
                for (int kk = 0; kk < 4; kk++) {
                    uint2 kb = *(const uint2*)&Kp[buf][(fn * 8 + gq) * 40 + (kk * 4 + tq) * 2];
                    uint32_t b2[2] = {kb.x, kb.y};
                    mma_tf32(s[fn], qa[kk], b2);
                }
            }

            // ---- mask (tail tile only) ----
            int tn = end - t0;
            if (tn < 32) {
                #pragma unroll
                for (int fn = 0; fn < 4; fn++) {
                    int c = fn * 8 + 2 * tq;
                    if (c >= tn)     { s[fn][0] = -1e30f; s[fn][2] = -1e30f; }
                    if (c + 1 >= tn) { s[fn][1] = -1e30f; s[fn][3] = -1e30f; }
                }
            }

            // ---- p = exp(s); accumulate l; stage paired tf32 ----
            {
                uint32_t* prow0 = &Pw[wid][gq * 40];
                uint32_t* prow1 = &Pw[wid][(gq + 8) * 40];
                int w0b = ((2 * tq) & 3) * 2 + (tq >> 1);
                #pragma unroll
                for (int fn = 0; fn < 4; fn++) {
                    float p0 = __expf(s[fn][0]), p1 = __expf(s[fn][1]);
                    float p2 = __expf(s[fn][2]), p3 = __expf(s[fn][3]);
                    l0 += p0 + p1; l1 += p2 + p3;
                    int w0 = fn * 8 + w0b;
                    prow0[w0] = f2tf(p0); prow0[w0 + 2] = f2tf(p1);
                    prow1[w0] = f2tf(p2); prow1[w0 + 2] = f2tf(p3);
                }
            }
            __syncwarp();

            // ---- O += P V ----
            #pragma unroll
            for (int kk = 0; kk < 4; kk++) {
                uint2 a0 = *(const uint2*)&Pw[wid][gq * 40 + (kk * 4 + tq) * 2];
                uint2 a1 = *(const uint2*)&Pw[wid][(gq + 8) * 40 + (kk * 4 + tq) * 2];
                uint32_t pa[4] = {a0.x, a1.x, a0.y, a1.y};
                #pragma unroll
                for (int fn = 0; fn < 4; fn++) {
                    uint32_t b2[2] = { Vs[buf][(kk * 8 + tq) * 40 + fn * 8 + gq],
                                       Vs[buf][(kk * 8 + tq + 4) * 40 + fn * 8 + gq] };
                    mma_tf32(o[fn], pa, b2);
                }
            }

            __syncthreads();                   // all reads of buf done
            if (tt + 2 < te) issue_tile(tt + 2, buf);
            buf ^= 1;
        }

        // ---- store partial l (per row) and partial o (fp32, unnormalized) ----
        l0 += __shfl_xor_sync(0xffffffffu, l0, 1);
        l0 += __shfl_xor_sync(0xffffffffu, l0, 2);
        l1 += __shfl_xor_sync(0xffffffffu, l1, 1);
        l1 += __shfl_xor_sync(0xffffffffu, l1, 2);
        if (tq == 0) {
            if (v0) LA[r0 * HEADS + hh] = l0;
            if (v1) LA[r1 * HEADS + hh] = l1;
        }
        #pragma unroll
        for (int fn = 0; fn < 4; fn++) {
            int col = hh * HEAD_DIM + fn * 8 + 2 * tq;
            if (v0) *(float2*)&OA[r0 * HIDDEN + col] = make_float2(o[fn][0], o[fn][1]);
            if (v1) *(float2*)&OA[r1 * HIDDEN + col] = make_float2(o[fn][2], o[fn][3]);
        }
    }
}

// ---------------------------------------------------------------------------
extern "C" void kernel_launch(void* const* d_in, const int* in_sizes, int n_in,
                              void* d_out, int out_size) {
    const float* x     = (const float*)d_in[0];
    const int*   batch = (const int*)  d_in[1];
    const float* Wq    = (const float*)d_in[2];
    const float* bq    = (const float*)d_in[3];
    const float* Wk    = (const float*)d_in[4];
    const float* bk    = (const float*)d_in[5];
    const float* Wv    = (const float*)d_in[6];
    const float* bv    = (const float*)d_in[7];
    const float* Wo    = (const float*)d_in[8];
    const float* bo    = (const float*)d_in[9];
    const float* gamma = (const float*)d_in[10];
    const float* beta  = (const float*)d_in[11];
    float* out = (float*)d_out;

    int n = in_sizes[0] / HIDDEN;   // 4096

    float *ph, *pq, *pk, *pv;
    cudaGetSymbolAddress((void**)&ph, g_h);
    cudaGetSymbolAddress((void**)&pq, g_q);
    cudaGetSymbolAddress((void**)&pk, g_k);
    cudaGetSymbolAddress((void**)&pv, g_v);

    prep_kernel<<<65, 256>>>(batch, n, Wq, Wk, Wv, Wo);
    ln_kernel<<<n, 256>>>(x, gamma, beta, ph);

    dim3 gqkv(HIDDEN / 64, n / 64, 3);
    gemm_qkv_kernel<<<gqkv, 128>>>(ph, bq, pq, bk, pk, bv, pv);

    attn_kernel<<<dim3(NGRAPH, HEADS, 8), 128>>>();

    dim3 go(HIDDEN / 64, n / 64, 1);
    gemm_o_kernel<<<go, 128>>>(bo, x, out);
}

// round 14
// speedup vs baseline: 1.3150x; 1.3150x over previous
#include <cuda_runtime.h>
#include <math.h>
#include <stdint.h>

#define HIDDEN   256
#define HEADS    8
#define HEAD_DIM 32
#define NGRAPH   16
#define MAXN     4096
#define LN_EPS   1e-5f
#define ATT_SCALE 0.17677669529663687f  /* 32^-0.5 */
#define QSCALE    0.25500526954188565f  /* ATT_SCALE * log2(e) */

// ---------------- device scratch (no allocation allowed) ----------------
// g_h, g_q, g_k, g_v hold tf32 BIT PATTERNS stored as float.
// g_att0/g_att1 hold fp32 UNNORMALIZED partial attention outputs (key halves).
__device__ float    g_h   [MAXN * HIDDEN];
__device__ float    g_q   [MAXN * HIDDEN];
__device__ float    g_k   [MAXN * HIDDEN];
__device__ float    g_v   [MAXN * HIDDEN];
__device__ float    g_att0[MAXN * HIDDEN];
__device__ float    g_att1[MAXN * HIDDEN];
__device__ float    g_l0  [MAXN * HEADS];
__device__ float    g_l1  [MAXN * HEADS];
__device__ uint32_t g_w4  [4 * HIDDEN * HIDDEN];   // Wq,Wk,Wv,Wo pre-converted tf32
__device__ int      g_batch[MAXN];
__device__ int      g_gstart[NGRAPH + 1];

// ---------------------------------------------------------------------------
// tf32 helpers
// ---------------------------------------------------------------------------
__device__ __forceinline__ uint32_t f2tf(float f) {
    uint32_t r;
    asm("cvt.rna.tf32.f32 %0, %1;" : "=r"(r) : "f"(f));
    return r;
}

__device__ __forceinline__ void mma_tf32(float* c, const uint32_t* a, const uint32_t* b) {
    asm volatile(
        "mma.sync.aligned.m16n8k8.row.col.f32.tf32.tf32.f32 "
        "{%0,%1,%2,%3}, {%4,%5,%6,%7}, {%8,%9}, {%0,%1,%2,%3};"
        : "+f"(c[0]), "+f"(c[1]), "+f"(c[2]), "+f"(c[3])
        : "r"(a[0]), "r"(a[1]), "r"(a[2]), "r"(a[3]), "r"(b[0]), "r"(b[1]));
}

// ---------------------------------------------------------------------------
// Kernel 1: prep. Block 0: batch dtype probe + segment offsets.
// Blocks 1..64: convert the 4 weight matrices to tf32 bits in g_w4.
// ---------------------------------------------------------------------------
__global__ void prep_kernel(const int* __restrict__ raw, int n,
                            const float* __restrict__ Wq, const float* __restrict__ Wk,
                            const float* __restrict__ Wv, const float* __restrict__ Wo) {
    int tid = threadIdx.x;
    if (blockIdx.x == 0) {
        __shared__ int s_odd, s_even;
        __shared__ int s_cnt[NGRAPH];
        if (tid == 0) { s_odd = 0; s_even = 0; }
        if (tid < NGRAPH) s_cnt[tid] = 0;
        __syncthreads();

        int odd = 0, even = 0;
        for (int i = tid; i < n; i += blockDim.x) {
            int v = raw[i];
            if (v != 0) { if (i & 1) odd = 1; else even = 1; }
        }
        if (odd)  atomicOr(&s_odd, 1);
        if (even) atomicOr(&s_even, 1);
        __syncthreads();

        bool is64 = (s_odd == 0) && (s_even != 0);
        for (int i = tid; i < n; i += blockDim.x) {
            int v = is64 ? raw[2 * i] : raw[i];
            v = min(max(v, 0), NGRAPH - 1);
            g_batch[i] = v;
            atomicAdd(&s_cnt[v], 1);
        }
        __syncthreads();
        if (tid == 0) {
            int acc = 0;
            for (int g = 0; g < NGRAPH; g++) { g_gstart[g] = acc; acc += s_cnt[g]; }
            g_gstart[NGRAPH] = acc;
        }
    } else {
        int blk = blockIdx.x - 1;
        #pragma unroll
        for (int it = 0; it < 4; it++) {
            int e4 = blk * 1024 + it * 256 + tid;
            int m = e4 >> 14;
            int off4 = e4 & 16383;
            const float4* src = (const float4*)(m == 0 ? Wq : m == 1 ? Wk : m == 2 ? Wv : Wo);
            float4 v = src[off4];
            uint4 w = make_uint4(f2tf(v.x), f2tf(v.y), f2tf(v.z), f2tf(v.w));
            *(uint4*)&g_w4[m * 65536 + off4 * 4] = w;
        }
    }
}

// ---------------------------------------------------------------------------
// Kernel 2: LayerNorm, writes tf32 bits. One block per row, 256 threads.
// ---------------------------------------------------------------------------
__global__ void ln_kernel(const float* __restrict__ x,
                          const float* __restrict__ gamma,
                          const float* __restrict__ beta,
                          float* __restrict__ h) {
    int row = blockIdx.x;
    int tid = threadIdx.x;
    float v = x[row * HIDDEN + tid];

    __shared__ float s1[8], s2[8];
    __shared__ float s_mu, s_rstd;
    float a = v, b = v * v;
    #pragma unroll
    for (int o = 16; o > 0; o >>= 1) {
        a += __shfl_xor_sync(0xffffffffu, a, o);
        b += __shfl_xor_sync(0xffffffffu, b, o);
    }
    if ((tid & 31) == 0) { s1[tid >> 5] = a; s2[tid >> 5] = b; }
    __syncthreads();
    if (tid == 0) {
        float sa = 0.f, sb = 0.f;
        #pragma unroll
        for (int i = 0; i < 8; i++) { sa += s1[i]; sb += s2[i]; }
        float mu  = sa * (1.0f / HIDDEN);
        float var = sb * (1.0f / HIDDEN) - mu * mu;
        s_mu = mu;
        s_rstd = rsqrtf(var + LN_EPS);
    }
    __syncthreads();
    float r = (v - s_mu) * s_rstd * gamma[tid] + beta[tid];
    h[row * HIDDEN + tid] = __uint_as_float(f2tf(r));
}

// ---------------------------------------------------------------------------
// tf32 GEMM core, double-buffered: C = (A @ W + bias) * oscale (+ residual).
// Block tile 64x64, BK=32, 128 threads = 4 warps (2x2), warp 32x32.
// NORM mode (gemm_o): A := (A0 + A1) * 1/(l0+l1) per (row, head=k0>>5),
// converted to tf32 in the load path — fuses the split-K attention combine.
// ---------------------------------------------------------------------------
template <bool RES, bool TF32OUT, bool NORM>
__device__ __forceinline__ void gemm_core(const float* __restrict__ A0f,
                                          const float* __restrict__ A1f,
                                          const float* __restrict__ l0p,
                                          const float* __restrict__ l1p,
                                          const uint32_t* __restrict__ W,
                                          const float* __restrict__ bias,
                                          const float* __restrict__ res,
                                          float* __restrict__ C, float oscale) {
    __shared__ uint32_t As[2][64 * 32];   // swizzled
    __shared__ uint32_t Bs[2][32 * 72];   // padded stride 72

    const int tid  = threadIdx.x;
    const int lane = tid & 31;
    const int wid  = tid >> 5;
    const int wm   = wid & 1;
    const int wn   = wid >> 1;
    const int bm   = blockIdx.y * 64;
    const int bn   = blockIdx.x * 64;

    const int ar  = tid >> 1;          // A row 0..63
    const int ach = tid & 1;           // A k-half
    const int bk  = tid >> 4;          // B k row 0..7 (stride 8)
    const int bn4 = tid & 15;          // B float4 col

    const int g   = lane >> 2;
    const int t   = lane & 3;
    const int swz = g << 2;

    const int arow = bm + ar;

    float acc[2][4][4] = {};

    auto load_a = [&](int k0, uint4* av) {
        if (NORM) {
            int head = k0 >> 5;
            float ls = l0p[arow * HEADS + head] + l1p[arow * HEADS + head];
            float li = (ls > 0.f) ? __frcp_rn(ls) : 0.f;
            const float4* Ap0 = (const float4*)&A0f[arow * HIDDEN + k0];
            const float4* Ap1 = (const float4*)&A1f[arow * HIDDEN + k0];
            #pragma unroll
            for (int i = 0; i < 4; i++) {
                float4 a = Ap0[ach * 4 + i];
                float4 b = Ap1[ach * 4 + i];
                av[i] = make_uint4(f2tf((a.x + b.x) * li), f2tf((a.y + b.y) * li),
                                   f2tf((a.z + b.z) * li), f2tf((a.w + b.w) * li));
            }
        } else {
            const uint4* Ap = (const uint4*)&A0f[arow * HIDDEN + k0];
            #pragma unroll
            for (int i = 0; i < 4; i++) av[i] = Ap[ach * 4 + i];
        }
    };

    uint4 av[4], bv[4];
    load_a(0, av);
    #pragma unroll
    for (int i = 0; i < 4; i++)
        bv[i] = *(const uint4*)&W[(bk + i * 8) * HIDDEN + bn + bn4 * 4];

    int buf = 0;
    for (int k0 = 0; k0 < HIDDEN; k0 += 32) {
        #pragma unroll
        for (int i = 0; i < 4; i++) {
            int c4 = ach * 4 + i;
            int phys = ar * 8 + (c4 ^ (ar & 7));
            *(uint4*)&As[buf][phys * 4] = av[i];
        }
        #pragma unroll
        for (int i = 0; i < 4; i++)
            *(uint4*)&Bs[buf][(bk + i * 8) * 72 + bn4 * 4] = bv[i];

        if (k0 + 32 < HIDDEN) {
            load_a(k0 + 32, av);
            #pragma unroll
            for (int i = 0; i < 4; i++)
                bv[i] = *(const uint4*)&W[(k0 + 32 + bk + i * 8) * HIDDEN + bn + bn4 * 4];
        }
        __syncthreads();

        #pragma unroll
        for (int kk = 0; kk < 4; kk++) {
            uint32_t afr[2][4];
            #pragma unroll
            for (int fm = 0; fm < 2; fm++) {
                int r0 = wm * 32 + fm * 16 + g;
                int r1 = r0 + 8;
                int c0 = kk * 8 + t;
                int c1 = c0 + 4;
                afr[fm][0] = As[buf][r0 * 32 + (c0 ^ swz)];
                afr[fm][1] = As[buf][r1 * 32 + (c0 ^ swz)];
                afr[fm][2] = As[buf][r0 * 32 + (c1 ^ swz)];
                afr[fm][3] = As[buf][r1 * 32 + (c1 ^ swz)];
            }
            uint32_t bfr[4][2];
            #pragma unroll
            for (int fn = 0; fn < 4; fn++) {
                int n  = wn * 32 + fn * 8 + g;
                int kb = kk * 8 + t;
                bfr[fn][0] = Bs[buf][kb * 72 + n];
                bfr[fn][1] = Bs[buf][(kb + 4) * 72 + n];
            }
            #pragma unroll
            for (int fm = 0; fm < 2; fm++)
                #pragma unroll
                for (int fn = 0; fn < 4; fn++)
                    mma_tf32(acc[fm][fn], afr[fm], bfr[fn]);
        }
        buf ^= 1;
    }

    #pragma unroll
    for (int fm = 0; fm < 2; fm++) {
        int row0 = bm + wm * 32 + fm * 16 + g;
        int row1 = row0 + 8;
        #pragma unroll
        for (int fn = 0; fn < 4; fn++) {
            int col = bn + wn * 32 + fn * 8 + t * 2;
            float2 bb = *(const float2*)&bias[col];
            float2 c0 = make_float2((acc[fm][fn][0] + bb.x) * oscale,
                                    (acc[fm][fn][1] + bb.y) * oscale);
            float2 c1 = make_float2((acc[fm][fn][2] + bb.x) * oscale,
                                    (acc[fm][fn][3] + bb.y) * oscale);
            if (RES) {
                float2 r0 = *(const float2*)&res[row0 * HIDDEN + col];
                float2 r1 = *(const float2*)&res[row1 * HIDDEN + col];
                c0.x += r0.x; c0.y += r0.y;
                c1.x += r1.x; c1.y += r1.y;
            }
            if (TF32OUT) {
                c0.x = __uint_as_float(f2tf(c0.x)); c0.y = __uint_as_float(f2tf(c0.y));
                c1.x = __uint_as_float(f2tf(c1.x)); c1.y = __uint_as_float(f2tf(c1.y));
            }
            *(float2*)&C[row0 * HIDDEN + col] = c0;
            *(float2*)&C[row1 * HIDDEN + col] = c1;
        }
    }
}

__global__ void __launch_bounds__(128)
gemm_qkv_kernel(const float* __restrict__ A,
                const float* __restrict__ bq, float* __restrict__ Cq,
                const float* __restrict__ bk, float* __restrict__ Ck,
                const float* __restrict__ bv, float* __restrict__ Cv) {
    const float* b; float* C; const uint32_t* W; float sc;
    if (blockIdx.z == 0)      { W = g_w4;             b = bq; C = Cq; sc = QSCALE; }
    else if (blockIdx.z == 1) { W = g_w4 + 65536;     b = bk; C = Ck; sc = 1.0f; }
    else                      { W = g_w4 + 2 * 65536; b = bv; C = Cv; sc = 1.0f; }
    gemm_core<false, true, false>(A, nullptr, nullptr, nullptr, W, b, nullptr, C, sc);
}

__global__ void __launch_bounds__(128)
gemm_o_kernel(const float* __restrict__ bias, const float* __restrict__ res,
              float* __restrict__ C) {
    gemm_core<true, false, true>(g_att0, g_att1, g_l0, g_l1,
                                 g_w4 + 3 * 65536, bias, res, C, 1.0f);
}

// ---------------------------------------------------------------------------
// Kernel 4: split-K tensor-core attention, no running max (scores O(1)).
// grid = (NGRAPH, HEADS, 8): z>>1 = query quarter, z&1 = key half.
// Each block accumulates UNNORMALIZED partial o and l over its half of the
// key tiles and writes them to its half's buffer (disjoint -> deterministic,
// no atomics). gemm_o combines: o = (o0+o1)/(l0+l1).
// Q is pre-scaled by ATT_SCALE*log2(e) so p = exp2f(s) == e^(ATT_SCALE*qk).
// K smem: paired {k[c],k[c+4]} uint2 stride 20 (LDS.64 conflict-free).
// V smem: [j][d] stride 40 (LDS.32 conflict-free: bank = 8*((tq+fn)&3)+gq).
// ---------------------------------------------------------------------------
__global__ void __launch_bounds__(128)
attn_kernel() {
    __shared__ uint2    Kp[2][32][20];
    __shared__ uint32_t Vs[2][32 * 40];
    __shared__ uint32_t Pw[4][16 * 40];

    const int gb = blockIdx.x, hh = blockIdx.y;
    const int half = blockIdx.z & 1, qz = blockIdx.z >> 1;
    const int start = g_gstart[gb], end = g_gstart[gb + 1];
    const int n = end - start;
    const int tid = threadIdx.x, lane = tid & 31, wid = tid >> 5;
    const int gq = lane >> 2, tq = lane & 3;
    const uint32_t* Q = (const uint32_t*)g_q;
    const uint32_t* K = (const uint32_t*)g_k;
    const uint32_t* V = (const uint32_t*)g_v;
    float* OA = half ? g_att1 : g_att0;
    float* LA = half ? g_l1   : g_l0;

    // key-tile range for this half
    const int T = (n + 31) >> 5;
    const int tb = half ? (T >> 1) : 0;
    const int te = half ? T : (T >> 1);

    const int lj = tid >> 2;
    const int lb = tid & 3;
    const int kvoff = hh * HEAD_DIM + lb * 8;

    for (int qt = qz * 64; qt < n; qt += 256) {
        const int r0 = start + qt + wid * 16 + gq, r1 = r0 + 8;
        const bool v0 = r0 < end, v1 = r1 < end;

        uint32_t qa[4][4];
        #pragma unroll
        for (int kk = 0; kk < 4; kk++) {
            int c = hh * HEAD_DIM + kk * 8 + tq;
            qa[kk][0] = v0 ? Q[r0 * HIDDEN + c]     : 0u;
            qa[kk][1] = v1 ? Q[r1 * HIDDEN + c]     : 0u;
            qa[kk][2] = v0 ? Q[r0 * HIDDEN + c + 4] : 0u;
            qa[kk][3] = v1 ? Q[r1 * HIDDEN + c + 4] : 0u;
        }

        float o[4][4] = {};
        float l0 = 0.f, l1 = 0.f;

        uint4 kf0, kf1, vf0, vf1;
        if (tb < te) {
            int row = start + tb * 32 + lj;
            uint4 z = make_uint4(0u, 0u, 0u, 0u);
            kf0 = kf1 = vf0 = vf1 = z;
            if (row < end) {
                const uint4* kp = (const uint4*)&K[row * HIDDEN + kvoff];
                kf0 = kp[0]; kf1 = kp[1];
                const uint4* vp = (const uint4*)&V[row * HIDDEN + kvoff];
                vf0 = vp[0]; vf1 = vp[1];
            }
        }

        int buf = 0;
        for (int tt = tb; tt < te; tt++) {
            const int t0 = start + tt * 32;
            {
                uint2* kd = &Kp[buf][lj][lb * 4];
                kd[0] = make_uint2(kf0.x, kf1.x);
                kd[1] = make_uint2(kf0.y, kf1.y);
                kd[2] = make_uint2(kf0.z, kf1.z);
                kd[3] = make_uint2(kf0.w, kf1.w);
                *(uint4*)&Vs[buf][lj * 40 + lb * 8]     = vf0;
                *(uint4*)&Vs[buf][lj * 40 + lb * 8 + 4] = vf1;
            }
            if (tt + 1 < te) {
                int row = t0 + 32 + lj;
                uint4 z = make_uint4(0u, 0u, 0u, 0u);
                kf0 = kf1 = vf0 = vf1 = z;
                if (row < end) {
                    const uint4* kp = (const uint4*)&K[row * HIDDEN + kvoff];
                    kf0 = kp[0]; kf1 = kp[1];
                    const uint4* vp = (const uint4*)&V[row * HIDDEN + kvoff];
                    vf0 = vp[0]; vf1 = vp[1];
                }
            }
            __syncthreads();

            // ---- S = Q K^T (Q pre-scaled by QSCALE) ----
            float s[4][4] = {};
            #pragma unroll
            for (int fn = 0; fn < 4; fn++) {
                #pragma unroll
                for (int kk = 0; kk < 4; kk++) {
                    uint2 kb = Kp[buf][fn * 8 + gq][kk * 4 + tq];
                    uint32_t b2[2] = {kb.x, kb.y};
                    mma_tf32(s[fn], qa[kk], b2);
                }
            }

            // ---- mask (tail tile only) ----
            int tn = end - t0;
            if (tn < 32) {
                #pragma unroll
                for (int fn = 0; fn < 4; fn++) {
                    int c = fn * 8 + 2 * tq;
                    if (c >= tn)     { s[fn][0] = -1e30f; s[fn][2] = -1e30f; }
                    if (c + 1 >= tn) { s[fn][1] = -1e30f; s[fn][3] = -1e30f; }
                }
            }

            // ---- p = exp2(s); accumulate l; stage paired tf32 ----
            {
                uint32_t* prow0 = &Pw[wid][gq * 40];
                uint32_t* prow1 = &Pw[wid][(gq + 8) * 40];
                int w0b = ((2 * tq) & 3) * 2 + (tq >> 1);
                #pragma unroll
                for (int fn = 0; fn < 4; fn++) {
                    float p0 = exp2f(s[fn][0]), p1 = exp2f(s[fn][1]);
                    float p2 = exp2f(s[fn][2]), p3 = exp2f(s[fn][3]);
                    l0 += p0 + p1; l1 += p2 + p3;
                    int w0 = fn * 8 + w0b;
                    prow0[w0] = f2tf(p0); prow0[w0 + 2] = f2tf(p1);
                    prow1[w0] = f2tf(p2); prow1[w0 + 2] = f2tf(p3);
                }
            }
            __syncwarp();

            // ---- O += P V ----
            #pragma unroll
            for (int kk = 0; kk < 4; kk++) {
                uint2 a0 = *(const uint2*)&Pw[wid][gq * 40 + (kk * 4 + tq) * 2];
                uint2 a1 = *(const uint2*)&Pw[wid][(gq + 8) * 40 + (kk * 4 + tq) * 2];
                uint32_t pa[4] = {a0.x, a1.x, a0.y, a1.y};
                #pragma unroll
                for (int fn = 0; fn < 4; fn++) {
                    uint32_t b2[2] = { Vs[buf][(kk * 8 + tq) * 40 + fn * 8 + gq],
                                       Vs[buf][(kk * 8 + tq + 4) * 40 + fn * 8 + gq] };
                    mma_tf32(o[fn], pa, b2);
                }
            }
            buf ^= 1;
        }

        // ---- store partial l (per row) and partial o (fp32, unnormalized) ----
        l0 += __shfl_xor_sync(0xffffffffu, l0, 1);
        l0 += __shfl_xor_sync(0xffffffffu, l0, 2);
        l1 += __shfl_xor_sync(0xffffffffu, l1, 1);
        l1 += __shfl_xor_sync(0xffffffffu, l1, 2);
        if (tq == 0) {
            if (v0) LA[r0 * HEADS + hh] = l0;
            if (v1) LA[r1 * HEADS + hh] = l1;
        }
        #pragma unroll
        for (int fn = 0; fn < 4; fn++) {
            int col = hh * HEAD_DIM + fn * 8 + 2 * tq;
            if (v0) *(float2*)&OA[r0 * HIDDEN + col] = make_float2(o[fn][0], o[fn][1]);
            if (v1) *(float2*)&OA[r1 * HIDDEN + col] = make_float2(o[fn][2], o[fn][3]);
        }
    }
}

// ---------------------------------------------------------------------------
extern "C" void kernel_launch(void* const* d_in, const int* in_sizes, int n_in,
                              void* d_out, int out_size) {
    const float* x     = (const float*)d_in[0];
    const int*   batch = (const int*)  d_in[1];
    const float* Wq    = (const float*)d_in[2];
    const float* bq    = (const float*)d_in[3];
    const float* Wk    = (const float*)d_in[4];
    const float* bk    = (const float*)d_in[5];
    const float* Wv    = (const float*)d_in[6];
    const float* bv    = (const float*)d_in[7];
    const float* Wo    = (const float*)d_in[8];
    const float* bo    = (const float*)d_in[9];
    const float* gamma = (const float*)d_in[10];
    const float* beta  = (const float*)d_in[11];
    float* out = (float*)d_out;

    int n = in_sizes[0] / HIDDEN;   // 4096

    float *ph, *pq, *pk, *pv;
    cudaGetSymbolAddress((void**)&ph, g_h);
    cudaGetSymbolAddress((void**)&pq, g_q);
    cudaGetSymbolAddress((void**)&pk, g_k);
    cudaGetSymbolAddress((void**)&pv, g_v);

    prep_kernel<<<65, 256>>>(batch, n, Wq, Wk, Wv, Wo);
    ln_kernel<<<n, 256>>>(x, gamma, beta, ph);

    dim3 gqkv(HIDDEN / 64, n / 64, 3);
    gemm_qkv_kernel<<<gqkv, 128>>>(ph, bq, pq, bk, pk, bv, pv);

    attn_kernel<<<dim3(NGRAPH, HEADS, 8), 128>>>();

    dim3 go(HIDDEN / 64, n / 64, 1);
    gemm_o_kernel<<<go, 128>>>(bo, x, out);
}

// round 15
// speedup vs baseline: 1.5239x; 1.1589x over previous
#include <cuda_runtime.h>
#include <math.h>
#include <stdint.h>

#define HIDDEN   256
#define HEADS    8
#define HEAD_DIM 32
#define NGRAPH   16
#define MAXN     4096
#define LN_EPS   1e-5f
#define ATT_SCALE 0.17677669529663687f  /* 32^-0.5 */
#define QSCALE    0.25500526954188565f  /* ATT_SCALE * log2(e) */

// ---------------- device scratch (no allocation allowed) ----------------
// g_q, g_k, g_v hold tf32 BIT PATTERNS stored as float.
// g_att0/g_att1 hold fp32 UNNORMALIZED partial attention outputs (key halves).
__device__ float    g_q   [MAXN * HIDDEN];
__device__ float    g_k   [MAXN * HIDDEN];
__device__ float    g_v   [MAXN * HIDDEN];
__device__ float    g_att0[MAXN * HIDDEN];
__device__ float    g_att1[MAXN * HIDDEN];
__device__ float    g_l0  [MAXN * HEADS];
__device__ float    g_l1  [MAXN * HEADS];
__device__ float    g_mu  [MAXN];
__device__ float    g_rstd[MAXN];
__device__ int      g_batch[MAXN];
__device__ int      g_gstart[NGRAPH + 1];

// ---------------------------------------------------------------------------
// tf32 helpers
// ---------------------------------------------------------------------------
__device__ __forceinline__ uint32_t f2tf(float f) {
    uint32_t r;
    asm("cvt.rna.tf32.f32 %0, %1;" : "=r"(r) : "f"(f));
    return r;
}

__device__ __forceinline__ void mma_tf32(float* c, const uint32_t* a, const uint32_t* b) {
    asm volatile(
        "mma.sync.aligned.m16n8k8.row.col.f32.tf32.tf32.f32 "
        "{%0,%1,%2,%3}, {%4,%5,%6,%7}, {%8,%9}, {%0,%1,%2,%3};"
        : "+f"(c[0]), "+f"(c[1]), "+f"(c[2]), "+f"(c[3])
        : "r"(a[0]), "r"(a[1]), "r"(a[2]), "r"(a[3]), "r"(b[0]), "r"(b[1]));
}

// ---------------------------------------------------------------------------
// Kernel 1: prep. Block 0: batch dtype probe + segment offsets.
// Blocks 1..512: per-row LayerNorm stats (mu, rstd), one warp per row.
// ---------------------------------------------------------------------------
__global__ void prep_kernel(const int* __restrict__ raw, int n,
                            const float* __restrict__ x) {
    int tid = threadIdx.x;
    if (blockIdx.x == 0) {
        __shared__ int s_odd, s_even;
        __shared__ int s_cnt[NGRAPH];
        if (tid == 0) { s_odd = 0; s_even = 0; }
        if (tid < NGRAPH) s_cnt[tid] = 0;
        __syncthreads();

        int odd = 0, even = 0;
        for (int i = tid; i < n; i += blockDim.x) {
            int v = raw[i];
            if (v != 0) { if (i & 1) odd = 1; else even = 1; }
        }
        if (odd)  atomicOr(&s_odd, 1);
        if (even) atomicOr(&s_even, 1);
        __syncthreads();

        bool is64 = (s_odd == 0) && (s_even != 0);
        for (int i = tid; i < n; i += blockDim.x) {
            int v = is64 ? raw[2 * i] : raw[i];
            v = min(max(v, 0), NGRAPH - 1);
            g_batch[i] = v;
            atomicAdd(&s_cnt[v], 1);
        }
        __syncthreads();
        if (tid == 0) {
            int acc = 0;
            for (int g = 0; g < NGRAPH; g++) { g_gstart[g] = acc; acc += s_cnt[g]; }
            g_gstart[NGRAPH] = acc;
        }
    } else {
        // one warp per row: 8 warps/block, 512 blocks -> 4096 rows
        int wid  = tid >> 5, lane = tid & 31;
        int row  = (blockIdx.x - 1) * 8 + wid;
        if (row < n) {
            float a = 0.f, b = 0.f;
            #pragma unroll
            for (int i = 0; i < 8; i++) {
                float v = x[row * HIDDEN + lane + 32 * i];
                a += v; b += v * v;
            }
            #pragma unroll
            for (int o = 16; o > 0; o >>= 1) {
                a += __shfl_xor_sync(0xffffffffu, a, o);
                b += __shfl_xor_sync(0xffffffffu, b, o);
            }
            if (lane == 0) {
                float mu  = a * (1.0f / HIDDEN);
                float var = b * (1.0f / HIDDEN) - mu * mu;
                g_mu[row]   = mu;
                g_rstd[row] = rsqrtf(var + LN_EPS);
            }
        }
    }
}

// ---------------------------------------------------------------------------
// tf32 GEMM core, double-buffered: C = (LN?(A) @ tf32(W) + bias) * oscale.
// Block tile 64x64, BK=32, 128 threads = 4 warps (2x2), warp 32x32.
// LNLOAD: A := ((x - mu) * rstd * gamma + beta) per element, tf32 on load.
// NORM  : A := (A0 + A1) * 1/(l0+l1) per (row, head) — split-K combine.
// W is raw fp32, converted to tf32 in the B-load path.
// ---------------------------------------------------------------------------
template <bool RES, bool TF32OUT, bool NORM, bool LNLOAD>
__device__ __forceinline__ void gemm_core(const float* __restrict__ A0f,
                                          const float* __restrict__ A1f,
                                          const float* __restrict__ l0p,
                                          const float* __restrict__ l1p,
                                          const float* __restrict__ gamma,
                                          const float* __restrict__ beta,
                                          const float* __restrict__ W,
                                          const float* __restrict__ bias,
                                          const float* __restrict__ res,
                                          float* __restrict__ C, float oscale) {
    __shared__ uint32_t As[2][64 * 32];   // swizzled
    __shared__ uint32_t Bs[2][32 * 72];   // padded stride 72

    const int tid  = threadIdx.x;
    const int lane = tid & 31;
    const int wid  = tid >> 5;
    const int wm   = wid & 1;
    const int wn   = wid >> 1;
    const int bm   = blockIdx.y * 64;
    const int bn   = blockIdx.x * 64;

    const int ar  = tid >> 1;          // A row 0..63
    const int ach = tid & 1;           // A k-half
    const int bk  = tid >> 4;          // B k row 0..7 (stride 8)
    const int bn4 = tid & 15;          // B float4 col

    const int g   = lane >> 2;
    const int t   = lane & 3;
    const int swz = g << 2;

    const int arow = bm + ar;

    float mu = 0.f, rs = 0.f;
    if (LNLOAD) { mu = g_mu[arow]; rs = g_rstd[arow]; }

    float acc[2][4][4] = {};

    auto load_a = [&](int k0, uint4* av) {
        if (NORM) {
            int head = k0 >> 5;
            float ls = l0p[arow * HEADS + head] + l1p[arow * HEADS + head];
            float li = (ls > 0.f) ? __frcp_rn(ls) : 0.f;
            const float4* Ap0 = (const float4*)&A0f[arow * HIDDEN + k0];
            const float4* Ap1 = (const float4*)&A1f[arow * HIDDEN + k0];
            #pragma unroll
            for (int i = 0; i < 4; i++) {
                float4 a = Ap0[ach * 4 + i];
                float4 b = Ap1[ach * 4 + i];
                av[i] = make_uint4(f2tf((a.x + b.x) * li), f2tf((a.y + b.y) * li),
                                   f2tf((a.z + b.z) * li), f2tf((a.w + b.w) * li));
            }
        } else if (LNLOAD) {
            const float4* Ap = (const float4*)&A0f[arow * HIDDEN + k0];
            const float4* Gp = (const float4*)&gamma[k0];
            const float4* Bp = (const float4*)&beta[k0];
            #pragma unroll
            for (int i = 0; i < 4; i++) {
                float4 a  = Ap[ach * 4 + i];
                float4 gm = Gp[ach * 4 + i];
                float4 bt = Bp[ach * 4 + i];
                av[i] = make_uint4(f2tf((a.x - mu) * rs * gm.x + bt.x),
                                   f2tf((a.y - mu) * rs * gm.y + bt.y),
                                   f2tf((a.z - mu) * rs * gm.z + bt.z),
                                   f2tf((a.w - mu) * rs * gm.w + bt.w));
            }
        } else {
            const uint4* Ap = (const uint4*)&A0f[arow * HIDDEN + k0];
            #pragma unroll
            for (int i = 0; i < 4; i++) av[i] = Ap[ach * 4 + i];
        }
    };

    auto load_b = [&](int k0, uint4* bv) {
        #pragma unroll
        for (int i = 0; i < 4; i++) {
            float4 w = *(const float4*)&W[(k0 + bk + i * 8) * HIDDEN + bn + bn4 * 4];
            bv[i] = make_uint4(f2tf(w.x), f2tf(w.y), f2tf(w.z), f2tf(w.w));
        }
    };

    uint4 av[4], bv[4];
    load_a(0, av);
    load_b(0, bv);

    int buf = 0;
    for (int k0 = 0; k0 < HIDDEN; k0 += 32) {
        #pragma unroll
        for (int i = 0; i < 4; i++) {
            int c4 = ach * 4 + i;
            int phys = ar * 8 + (c4 ^ (ar & 7));
            *(uint4*)&As[buf][phys * 4] = av[i];
        }
        #pragma unroll
        for (int i = 0; i < 4; i++)
            *(uint4*)&Bs[buf][(bk + i * 8) * 72 + bn4 * 4] = bv[i];

        if (k0 + 32 < HIDDEN) {
            load_a(k0 + 32, av);
            load_b(k0 + 32, bv);
        }
        __syncthreads();

        #pragma unroll
        for (int kk = 0; kk < 4; kk++) {
            uint32_t afr[2][4];
            #pragma unroll
            for (int fm = 0; fm < 2; fm++) {
                int r0 = wm * 32 + fm * 16 + g;
                int r1 = r0 + 8;
                int c0 = kk * 8 + t;
                int c1 = c0 + 4;
                afr[fm][0] = As[buf][r0 * 32 + (c0 ^ swz)];
                afr[fm][1] = As[buf][r1 * 32 + (c0 ^ swz)];
                afr[fm][2] = As[buf][r0 * 32 + (c1 ^ swz)];
                afr[fm][3] = As[buf][r1 * 32 + (c1 ^ swz)];
            }
            uint32_t bfr[4][2];
            #pragma unroll
            for (int fn = 0; fn < 4; fn++) {
                int n  = wn * 32 + fn * 8 + g;
                int kb = kk * 8 + t;
                bfr[fn][0] = Bs[buf][kb * 72 + n];
                bfr[fn][1] = Bs[buf][(kb + 4) * 72 + n];
            }
            #pragma unroll
            for (int fm = 0; fm < 2; fm++)
                #pragma unroll
                for (int fn = 0; fn < 4; fn++)
                    mma_tf32(acc[fm][fn], afr[fm], bfr[fn]);
        }
        buf ^= 1;
    }

    #pragma unroll
    for (int fm = 0; fm < 2; fm++) {
        int row0 = bm + wm * 32 + fm * 16 + g;
        int row1 = row0 + 8;
        #pragma unroll
        for (int fn = 0; fn < 4; fn++) {
            int col = bn + wn * 32 + fn * 8 + t * 2;
            float2 bb = *(const float2*)&bias[col];
            float2 c0 = make_float2((acc[fm][fn][0] + bb.x) * oscale,
                                    (acc[fm][fn][1] + bb.y) * oscale);
            float2 c1 = make_float2((acc[fm][fn][2] + bb.x) * oscale,
                                    (acc[fm][fn][3] + bb.y) * oscale);
            if (RES) {
                float2 r0 = *(const float2*)&res[row0 * HIDDEN + col];
                float2 r1 = *(const float2*)&res[row1 * HIDDEN + col];
                c0.x += r0.x; c0.y += r0.y;
                c1.x += r1.x; c1.y += r1.y;
            }
            if (TF32OUT) {
                c0.x = __uint_as_float(f2tf(c0.x)); c0.y = __uint_as_float(f2tf(c0.y));
                c1.x = __uint_as_float(f2tf(c1.x)); c1.y = __uint_as_float(f2tf(c1.y));
            }
            *(float2*)&C[row0 * HIDDEN + col] = c0;
            *(float2*)&C[row1 * HIDDEN + col] = c1;
        }
    }
}

__global__ void __launch_bounds__(128)
gemm_qkv_kernel(const float* __restrict__ x,
                const float* __restrict__ gamma, const float* __restrict__ beta,
                const float* __restrict__ Wq, const float* __restrict__ bq, float* __restrict__ Cq,
                const float* __restrict__ Wk, const float* __restrict__ bk, float* __restrict__ Ck,
                const float* __restrict__ Wv, const float* __restrict__ bv, float* __restrict__ Cv) {
    const float* W; const float* b; float* C; float sc;
    if (blockIdx.z == 0)      { W = Wq; b = bq; C = Cq; sc = QSCALE; }
    else if (blockIdx.z == 1) { W = Wk; b = bk; C = Ck; sc = 1.0f; }
    else                      { W = Wv; b = bv; C = Cv; sc = 1.0f; }
    gemm_core<false, true, false, true>(x, nullptr, nullptr, nullptr,
                                        gamma, beta, W, b, nullptr, C, sc);
}

__global__ void __launch_bounds__(128)
gemm_o_kernel(const float* __restrict__ Wo,
              const float* __restrict__ bias, const float* __restrict__ res,
              float* __restrict__ C) {
    gemm_core<true, false, true, false>(g_att0, g_att1, g_l0, g_l1,
                                        nullptr, nullptr, Wo, bias, res, C, 1.0f);
}

// ---------------------------------------------------------------------------
// Kernel 4: split-K tensor-core attention, no running max (scores O(1)).
// grid = (NGRAPH, HEADS, 8): z>>1 = query quarter, z&1 = key half.
// Q is pre-scaled by ATT_SCALE*log2(e) so p = exp2f(s) == e^(ATT_SCALE*qk).
// K smem: paired {k[c],k[c+4]} uint2 stride 20 (LDS.64 conflict-free).
// V smem: [j][d] stride 40 (LDS.32 conflict-free).
// ---------------------------------------------------------------------------
__global__ void __launch_bounds__(128)
attn_kernel() {
    __shared__ uint2    Kp[2][32][20];
    __shared__ uint32_t Vs[2][32 * 40];
    __shared__ uint32_t Pw[4][16 * 40];

    const int gb = blockIdx.x, hh = blockIdx.y;
    const int half = blockIdx.z & 1, qz = blockIdx.z >> 1;
    const int start = g_gstart[gb], end = g_gstart[gb + 1];
    const int n = end - start;
    const int tid = threadIdx.x, lane = tid & 31, wid = tid >> 5;
    const int gq = lane >> 2, tq = lane & 3;
    const uint32_t* Q = (const uint32_t*)g_q;
    const uint32_t* K = (const uint32_t*)g_k;
    const uint32_t* V = (const uint32_t*)g_v;
    float* OA = half ? g_att1 : g_att0;
    float* LA = half ? g_l1   : g_l0;

    const int T = (n + 31) >> 5;
    const int tb = half ? (T >> 1) : 0;
    const int te = half ? T : (T >> 1);

    const int lj = tid >> 2;
    const int lb = tid & 3;
    const int kvoff = hh * HEAD_DIM + lb * 8;

    for (int qt = qz * 64; qt < n; qt += 256) {
        const int r0 = start + qt + wid * 16 + gq, r1 = r0 + 8;
        const bool v0 = r0 < end, v1 = r1 < end;

        uint32_t qa[4][4];
        #pragma unroll
        for (int kk = 0; kk < 4; kk++) {
            int c = hh * HEAD_DIM + kk * 8 + tq;
            qa[kk][0] = v0 ? Q[r0 * HIDDEN + c]     : 0u;
            qa[kk][1] = v1 ? Q[r1 * HIDDEN + c]     : 0u;
            qa[kk][2] = v0 ? Q[r0 * HIDDEN + c + 4] : 0u;
            qa[kk][3] = v1 ? Q[r1 * HIDDEN + c + 4] : 0u;
        }

        float o[4][4] = {};
        float l0 = 0.f, l1 = 0.f;

        uint4 kf0, kf1, vf0, vf1;
        if (tb < te) {
            int row = start + tb * 32 + lj;
            uint4 z = make_uint4(0u, 0u, 0u, 0u);
            kf0 = kf1 = vf0 = vf1 = z;
            if (row < end) {
                const uint4* kp = (const uint4*)&K[row * HIDDEN + kvoff];
                kf0 = kp[0]; kf1 = kp[1];
                const uint4* vp = (const uint4*)&V[row * HIDDEN + kvoff];
                vf0 = vp[0]; vf1 = vp[1];
            }
        }

        int buf = 0;
        for (int tt = tb; tt < te; tt++) {
            const int t0 = start + tt * 32;
            {
                uint2* kd = &Kp[buf][lj][lb * 4];
                kd[0] = make_uint2(kf0.x, kf1.x);
                kd[1] = make_uint2(kf0.y, kf1.y);
                kd[2] = make_uint2(kf0.z, kf1.z);
                kd[3] = make_uint2(kf0.w, kf1.w);
                *(uint4*)&Vs[buf][lj * 40 + lb * 8]     = vf0;
                *(uint4*)&Vs[buf][lj * 40 + lb * 8 + 4] = vf1;
            }
            if (tt + 1 < te) {
                int row = t0 + 32 + lj;
                uint4 z = make_uint4(0u, 0u, 0u, 0u);
                kf0 = kf1 = vf0 = vf1 = z;
                if (row < end) {
                    const uint4* kp = (const uint4*)&K[row * HIDDEN + kvoff];
                    kf0 = kp[0]; kf1 = kp[1];
                    const uint4* vp = (const uint4*)&V[row * HIDDEN + kvoff];
                    vf0 = vp[0]; vf1 = vp[1];
                }
            }
            __syncthreads();

            // ---- S = Q K^T (Q pre-scaled by QSCALE) ----
            float s[4][4] = {};
            #pragma unroll
            for (int fn = 0; fn < 4; fn++) {
                #pragma unroll
                for (int kk = 0; kk < 4; kk++) {
                    uint2 kb = Kp[buf][fn * 8 + gq][kk * 4 + tq];
                    uint32_t b2[2] = {kb.x, kb.y};
                    mma_tf32(s[fn], qa[kk], b2);
                }
            }

            // ---- mask (tail tile only) ----
            int tn = end - t0;
            if (tn < 32) {
                #pragma unroll
                for (int fn = 0; fn < 4; fn++) {
                    int c = fn * 8 + 2 * tq;
                    if (c >= tn)     { s[fn][0] = -1e30f; s[fn][2] = -1e30f; }
                    if (c + 1 >= tn) { s[fn][1] = -1e30f; s[fn][3] = -1e30f; }
                }
            }

            // ---- p = exp2(s); accumulate l; stage paired tf32 ----
            {
                uint32_t* prow0 = &Pw[wid][gq * 40];
                uint32_t* prow1 = &Pw[wid][(gq + 8) * 40];
                int w0b = ((2 * tq) & 3) * 2 + (tq >> 1);
                #pragma unroll
                for (int fn = 0; fn < 4; fn++) {
                    float p0 = exp2f(s[fn][0]), p1 = exp2f(s[fn][1]);
                    float p2 = exp2f(s[fn][2]), p3 = exp2f(s[fn][3]);
                    l0 += p0 + p1; l1 += p2 + p3;
                    int w0 = fn * 8 + w0b;
                    prow0[w0] = f2tf(p0); prow0[w0 + 2] = f2tf(p1);
                    prow1[w0] = f2tf(p2); prow1[w0 + 2] = f2tf(p3);
                }
            }
            __syncwarp();

            // ---- O += P V ----
            #pragma unroll
            for (int kk = 0; kk < 4; kk++) {
                uint2 a0 = *(const uint2*)&Pw[wid][gq * 40 + (kk * 4 + tq) * 2];
                uint2 a1 = *(const uint2*)&Pw[wid][(gq + 8) * 40 + (kk * 4 + tq) * 2];
                uint32_t pa[4] = {a0.x, a1.x, a0.y, a1.y};
                #pragma unroll
                for (int fn = 0; fn < 4; fn++) {
                    uint32_t b2[2] = { Vs[buf][(kk * 8 + tq) * 40 + fn * 8 + gq],
                                       Vs[buf][(kk * 8 + tq + 4) * 40 + fn * 8 + gq] };
                    mma_tf32(o[fn], pa, b2);
                }
            }
            buf ^= 1;
        }

        // ---- store partial l (per row) and partial o (fp32, unnormalized) ----
        l0 += __shfl_xor_sync(0xffffffffu, l0, 1);
        l0 += __shfl_xor_sync(0xffffffffu, l0, 2);
        l1 += __shfl_xor_sync(0xffffffffu, l1, 1);
        l1 += __shfl_xor_sync(0xffffffffu, l1, 2);
        if (tq == 0) {
            if (v0) LA[r0 * HEADS + hh] = l0;
            if (v1) LA[r1 * HEADS + hh] = l1;
        }
        #pragma unroll
        for (int fn = 0; fn < 4; fn++) {
            int col = hh * HEAD_DIM + fn * 8 + 2 * tq;
            if (v0) *(float2*)&OA[r0 * HIDDEN + col] = make_float2(o[fn][0], o[fn][1]);
            if (v1) *(float2*)&OA[r1 * HIDDEN + col] = make_float2(o[fn][2], o[fn][3]);
        }
    }
}

// ---------------------------------------------------------------------------
extern "C" void kernel_launch(void* const* d_in, const int* in_sizes, int n_in,
                              void* d_out, int out_size) {
    const float* x     = (const float*)d_in[0];
    const int*   batch = (const int*)  d_in[1];
    const float* Wq    = (const float*)d_in[2];
    const float* bq    = (const float*)d_in[3];
    const float* Wk    = (const float*)d_in[4];
    const float* bk    = (const float*)d_in[5];
    const float* Wv    = (const float*)d_in[6];
    const float* bv    = (const float*)d_in[7];
    const float* Wo    = (const float*)d_in[8];
    const float* bo    = (const float*)d_in[9];
    const float* gamma = (const float*)d_in[10];
    const float* beta  = (const float*)d_in[11];
    float* out = (float*)d_out;

    int n = in_sizes[0] / HIDDEN;   // 4096

    float *pq, *pk, *pv;
    cudaGetSymbolAddress((void**)&pq, g_q);
    cudaGetSymbolAddress((void**)&pk, g_k);
    cudaGetSymbolAddress((void**)&pv, g_v);

    prep_kernel<<<1 + n / 8, 256>>>(batch, n, x);

    dim3 gqkv(HIDDEN / 64, n / 64, 3);
    gemm_qkv_kernel<<<gqkv, 128>>>(x, gamma, beta,
                                   Wq, bq, pq, Wk, bk, pk, Wv, bv, pv);

    attn_kernel<<<dim3(NGRAPH, HEADS, 8), 128>>>();

    dim3 go(HIDDEN / 64, n / 64, 1);
    gemm_o_kernel<<<go, 128>>>(Wo, bo, x, out);
}

// round 16
// speedup vs baseline: 1.6154x; 1.0601x over previous
#include <cuda_runtime.h>
#include <math.h>
#include <stdint.h>

#define HIDDEN   256
#define HEADS    8
#define HEAD_DIM 32
#define NGRAPH   16
#define MAXN     4096
#define LN_EPS   1e-5f
#define ATT_SCALE 0.17677669529663687f  /* 32^-0.5 */
#define QSCALE    0.25500526954188565f  /* ATT_SCALE * log2(e) */

// ---------------- device scratch (no allocation allowed) ----------------
// g_q, g_k, g_v hold tf32 BIT PATTERNS stored as float.
// g_att0/g_att1 hold fp32 UNNORMALIZED partial attention outputs (key halves).
__device__ float    g_q   [MAXN * HIDDEN];
__device__ float    g_k   [MAXN * HIDDEN];
__device__ float    g_v   [MAXN * HIDDEN];
__device__ float    g_att0[MAXN * HIDDEN];
__device__ float    g_att1[MAXN * HIDDEN];
__device__ float    g_l0  [MAXN * HEADS];
__device__ float    g_l1  [MAXN * HEADS];
__device__ float    g_mu  [MAXN];
__device__ float    g_rstd[MAXN];
__device__ int      g_batch[MAXN];
__device__ int      g_gstart[NGRAPH + 1];

// ---------------------------------------------------------------------------
// tf32 helpers
// ---------------------------------------------------------------------------
__device__ __forceinline__ uint32_t f2tf(float f) {
    uint32_t r;
    asm("cvt.rna.tf32.f32 %0, %1;" : "=r"(r) : "f"(f));
    return r;
}

__device__ __forceinline__ void mma_tf32(float* c, const uint32_t* a, const uint32_t* b) {
    asm volatile(
        "mma.sync.aligned.m16n8k8.row.col.f32.tf32.tf32.f32 "
        "{%0,%1,%2,%3}, {%4,%5,%6,%7}, {%8,%9}, {%0,%1,%2,%3};"
        : "+f"(c[0]), "+f"(c[1]), "+f"(c[2]), "+f"(c[3])
        : "r"(a[0]), "r"(a[1]), "r"(a[2]), "r"(a[3]), "r"(b[0]), "r"(b[1]));
}

// ---------------------------------------------------------------------------
// Kernel 1: prep. Block 0: batch dtype probe + segment offsets.
// Blocks 1..512: per-row LayerNorm stats (mu, rstd), one warp per row.
// ---------------------------------------------------------------------------
__global__ void prep_kernel(const int* __restrict__ raw, int n,
                            const float* __restrict__ x) {
    int tid = threadIdx.x;
    if (blockIdx.x == 0) {
        __shared__ int s_odd, s_even;
        __shared__ int s_cnt[NGRAPH];
        if (tid == 0) { s_odd = 0; s_even = 0; }
        if (tid < NGRAPH) s_cnt[tid] = 0;
        __syncthreads();

        int odd = 0, even = 0;
        for (int i = tid; i < n; i += blockDim.x) {
            int v = raw[i];
            if (v != 0) { if (i & 1) odd = 1; else even = 1; }
        }
        if (odd)  atomicOr(&s_odd, 1);
        if (even) atomicOr(&s_even, 1);
        __syncthreads();

        bool is64 = (s_odd == 0) && (s_even != 0);
        for (int i = tid; i < n; i += blockDim.x) {
            int v = is64 ? raw[2 * i] : raw[i];
            v = min(max(v, 0), NGRAPH - 1);
            g_batch[i] = v;
            atomicAdd(&s_cnt[v], 1);
        }
        __syncthreads();
        if (tid == 0) {
            int acc = 0;
            for (int g = 0; g < NGRAPH; g++) { g_gstart[g] = acc; acc += s_cnt[g]; }
            g_gstart[NGRAPH] = acc;
        }
    } else {
        int wid  = tid >> 5, lane = tid & 31;
        int row  = (blockIdx.x - 1) * 8 + wid;
        if (row < n) {
            float a = 0.f, b = 0.f;
            #pragma unroll
            for (int i = 0; i < 8; i++) {
                float v = x[row * HIDDEN + lane + 32 * i];
                a += v; b += v * v;
            }
            #pragma unroll
            for (int o = 16; o > 0; o >>= 1) {
                a += __shfl_xor_sync(0xffffffffu, a, o);
                b += __shfl_xor_sync(0xffffffffu, b, o);
            }
            if (lane == 0) {
                float mu  = a * (1.0f / HIDDEN);
                float var = b * (1.0f / HIDDEN) - mu * mu;
                g_mu[row]   = mu;
                g_rstd[row] = rsqrtf(var + LN_EPS);
            }
        }
    }
}

// ---------------------------------------------------------------------------
// tf32 GEMM core, double-buffered: C = (LN?(A) @ tf32(W) + bias) * oscale.
// FM = m16 fragments per warp in M. Block tile (FM*32) x 64, 128 threads,
// 4 warps (2x2), warp tile (FM*16) x 32.
// LNLOAD: A := ((x - mu) * rstd * gamma + beta), tf32 on load.
// NORM  : A := (A0 + A1) * 1/(l0+l1) per (row, head) — split-K combine.
// W is raw fp32, converted to tf32 in the B-load path.
// ---------------------------------------------------------------------------
template <bool RES, bool TF32OUT, bool NORM, bool LNLOAD, int FM>
__device__ __forceinline__ void gemm_core(const float* __restrict__ A0f,
                                          const float* __restrict__ A1f,
                                          const float* __restrict__ l0p,
                                          const float* __restrict__ l1p,
                                          const float* __restrict__ gamma,
                                          const float* __restrict__ beta,
                                          const float* __restrict__ W,
                                          const float* __restrict__ bias,
                                          const float* __restrict__ res,
                                          float* __restrict__ C, float oscale) {
    constexpr int MROWS = FM * 32;          // block tile M
    constexpr int TPR   = 128 / MROWS;      // threads per A row (2 or 4)
    constexpr int FPT   = 8 / TPR;          // float4 per thread per A row (4 or 2)

    __shared__ uint32_t As[2][MROWS * 32];  // swizzled
    __shared__ uint32_t Bs[2][32 * 72];     // padded stride 72

    const int tid  = threadIdx.x;
    const int lane = tid & 31;
    const int wid  = tid >> 5;
    const int wm   = wid & 1;
    const int wn   = wid >> 1;
    const int bm   = blockIdx.y * MROWS;
    const int bn   = blockIdx.x * 64;

    const int ar  = tid / TPR;              // A row
    const int ach = tid % TPR;              // A chunk within row
    const int bk  = tid >> 4;               // B k row 0..7 (stride 8)
    const int bn4 = tid & 15;               // B float4 col

    const int g   = lane >> 2;
    const int t   = lane & 3;
    const int swz = g << 2;

    const int arow = bm + ar;

    float mu = 0.f, rs = 0.f;
    if (LNLOAD) { mu = g_mu[arow]; rs = g_rstd[arow]; }

    float acc[FM][4][4] = {};

    auto load_a = [&](int k0, uint4* av) {
        if (NORM) {
            int head = k0 >> 5;
            float ls = l0p[arow * HEADS + head] + l1p[arow * HEADS + head];
            float li = (ls > 0.f) ? __frcp_rn(ls) : 0.f;
            const float4* Ap0 = (const float4*)&A0f[arow * HIDDEN + k0];
            const float4* Ap1 = (const float4*)&A1f[arow * HIDDEN + k0];
            #pragma unroll
            for (int i = 0; i < FPT; i++) {
                float4 a = Ap0[ach * FPT + i];
                float4 b = Ap1[ach * FPT + i];
                av[i] = make_uint4(f2tf((a.x + b.x) * li), f2tf((a.y + b.y) * li),
                                   f2tf((a.z + b.z) * li), f2tf((a.w + b.w) * li));
            }
        } else if (LNLOAD) {
            const float4* Ap = (const float4*)&A0f[arow * HIDDEN + k0];
            const float4* Gp = (const float4*)&gamma[k0];
            const float4* Bp = (const float4*)&beta[k0];
            #pragma unroll
            for (int i = 0; i < FPT; i++) {
                float4 a  = Ap[ach * FPT + i];
                float4 gm = Gp[ach * FPT + i];
                float4 bt = Bp[ach * FPT + i];
                av[i] = make_uint4(f2tf((a.x - mu) * rs * gm.x + bt.x),
                                   f2tf((a.y - mu) * rs * gm.y + bt.y),
                                   f2tf((a.z - mu) * rs * gm.z + bt.z),
                                   f2tf((a.w - mu) * rs * gm.w + bt.w));
            }
        } else {
            const uint4* Ap = (const uint4*)&A0f[arow * HIDDEN + k0];
            #pragma unroll
            for (int i = 0; i < FPT; i++) av[i] = Ap[ach * FPT + i];
        }
    };

    auto load_b = [&](int k0, uint4* bv) {
        #pragma unroll
        for (int i = 0; i < 4; i++) {
            float4 w = *(const float4*)&W[(k0 + bk + i * 8) * HIDDEN + bn + bn4 * 4];
            bv[i] = make_uint4(f2tf(w.x), f2tf(w.y), f2tf(w.z), f2tf(w.w));
        }
    };

    uint4 av[FPT], bv[4];
    load_a(0, av);
    load_b(0, bv);

    int buf = 0;
    for (int k0 = 0; k0 < HIDDEN; k0 += 32) {
        #pragma unroll
        for (int i = 0; i < FPT; i++) {
            int c4 = ach * FPT + i;
            int phys = ar * 8 + (c4 ^ (ar & 7));
            *(uint4*)&As[buf][phys * 4] = av[i];
        }
        #pragma unroll
        for (int i = 0; i < 4; i++)
            *(uint4*)&Bs[buf][(bk + i * 8) * 72 + bn4 * 4] = bv[i];

        if (k0 + 32 < HIDDEN) {
            load_a(k0 + 32, av);
            load_b(k0 + 32, bv);
        }
        __syncthreads();

        #pragma unroll
        for (int kk = 0; kk < 4; kk++) {
            uint32_t afr[FM][4];
            #pragma unroll
            for (int fm = 0; fm < FM; fm++) {
                int r0 = wm * (FM * 16) + fm * 16 + g;
                int r1 = r0 + 8;
                int c0 = kk * 8 + t;
                int c1 = c0 + 4;
                afr[fm][0] = As[buf][r0 * 32 + (c0 ^ swz)];
                afr[fm][1] = As[buf][r1 * 32 + (c0 ^ swz)];
                afr[fm][2] = As[buf][r0 * 32 + (c1 ^ swz)];
                afr[fm][3] = As[buf][r1 * 32 + (c1 ^ swz)];
            }
            uint32_t bfr[4][2];
            #pragma unroll
            for (int fn = 0; fn < 4; fn++) {
                int n  = wn * 32 + fn * 8 + g;
                int kb = kk * 8 + t;
                bfr[fn][0] = Bs[buf][kb * 72 + n];
                bfr[fn][1] = Bs[buf][(kb + 4) * 72 + n];
            }
            #pragma unroll
            for (int fm = 0; fm < FM; fm++)
                #pragma unroll
                for (int fn = 0; fn < 4; fn++)
                    mma_tf32(acc[fm][fn], afr[fm], bfr[fn]);
        }
        buf ^= 1;
    }

    #pragma unroll
    for (int fm = 0; fm < FM; fm++) {
        int row0 = bm + wm * (FM * 16) + fm * 16 + g;
        int row1 = row0 + 8;
        #pragma unroll
        for (int fn = 0; fn < 4; fn++) {
            int col = bn + wn * 32 + fn * 8 + t * 2;
            float2 bb = *(const float2*)&bias[col];
            float2 c0 = make_float2((acc[fm][fn][0] + bb.x) * oscale,
                                    (acc[fm][fn][1] + bb.y) * oscale);
            float2 c1 = make_float2((acc[fm][fn][2] + bb.x) * oscale,
                                    (acc[fm][fn][3] + bb.y) * oscale);
            if (RES) {
                float2 r0 = *(const float2*)&res[row0 * HIDDEN + col];
                float2 r1 = *(const float2*)&res[row1 * HIDDEN + col];
                c0.x += r0.x; c0.y += r0.y;
                c1.x += r1.x; c1.y += r1.y;
            }
            if (TF32OUT) {
                c0.x = __uint_as_float(f2tf(c0.x)); c0.y = __uint_as_float(f2tf(c0.y));
                c1.x = __uint_as_float(f2tf(c1.x)); c1.y = __uint_as_float(f2tf(c1.y));
            }
            *(float2*)&C[row0 * HIDDEN + col] = c0;
            *(float2*)&C[row1 * HIDDEN + col] = c1;
        }
    }
}

__global__ void __launch_bounds__(128)
gemm_qkv_kernel(const float* __restrict__ x,
                const float* __restrict__ gamma, const float* __restrict__ beta,
                const float* __restrict__ Wq, const float* __restrict__ bq, float* __restrict__ Cq,
                const float* __restrict__ Wk, const float* __restrict__ bk, float* __restrict__ Ck,
                const float* __restrict__ Wv, const float* __restrict__ bv, float* __restrict__ Cv) {
    const float* W; const float* b; float* C; float sc;
    if (blockIdx.z == 0)      { W = Wq; b = bq; C = Cq; sc = QSCALE; }
    else if (blockIdx.z == 1) { W = Wk; b = bk; C = Ck; sc = 1.0f; }
    else                      { W = Wv; b = bv; C = Cv; sc = 1.0f; }
    gemm_core<false, true, false, true, 2>(x, nullptr, nullptr, nullptr,
                                           gamma, beta, W, b, nullptr, C, sc);
}

__global__ void __launch_bounds__(128)
gemm_o_kernel(const float* __restrict__ Wo,
              const float* __restrict__ bias, const float* __restrict__ res,
              float* __restrict__ C) {
    gemm_core<true, false, true, false, 1>(g_att0, g_att1, g_l0, g_l1,
                                           nullptr, nullptr, Wo, bias, res, C, 1.0f);
}

// ---------------------------------------------------------------------------
// Kernel 4: split-K tensor-core attention, no running max (scores O(1)).
// grid = (NGRAPH, HEADS, 8): z>>1 = query quarter, z&1 = key half.
// Q is pre-scaled by ATT_SCALE*log2(e) so p = exp2f(s) == e^(ATT_SCALE*qk).
// K smem: paired {k[c],k[c+4]} uint2 stride 20 (LDS.64 conflict-free).
// V smem: [j][d] stride 40 (LDS.32 conflict-free).
// ---------------------------------------------------------------------------
__global__ void __launch_bounds__(128)
attn_kernel() {
    __shared__ uint2    Kp[2][32][20];
    __shared__ uint32_t Vs[2][32 * 40];
    __shared__ uint32_t Pw[4][16 * 40];

    const int gb = blockIdx.x, hh = blockIdx.y;
    const int half = blockIdx.z & 1, qz = blockIdx.z >> 1;
    const int start = g_gstart[gb], end = g_gstart[gb + 1];
    const int n = end - start;
    const int tid = threadIdx.x, lane = tid & 31, wid = tid >> 5;
    const int gq = lane >> 2, tq = lane & 3;
    const uint32_t* Q = (const uint32_t*)g_q;
    const uint32_t* K = (const uint32_t*)g_k;
    const uint32_t* V = (const uint32_t*)g_v;
    float* OA = half ? g_att1 : g_att0;
    float* LA = half ? g_l1   : g_l0;

    const int T = (n + 31) >> 5;
    const int tb = half ? (T >> 1) : 0;
    const int te = half ? T : (T >> 1);

    const int lj = tid >> 2;
    const int lb = tid & 3;
    const int kvoff = hh * HEAD_DIM + lb * 8;

    for (int qt = qz * 64; qt < n; qt += 256) {
        const int r0 = start + qt + wid * 16 + gq, r1 = r0 + 8;
        const bool v0 = r0 < end, v1 = r1 < end;

        uint32_t qa[4][4];
        #pragma unroll
        for (int kk = 0; kk < 4; kk++) {
            int c = hh * HEAD_DIM + kk * 8 + tq;
            qa[kk][0] = v0 ? Q[r0 * HIDDEN + c]     : 0u;
            qa[kk][1] = v1 ? Q[r1 * HIDDEN + c]     : 0u;
            qa[kk][2] = v0 ? Q[r0 * HIDDEN + c + 4] : 0u;
            qa[kk][3] = v1 ? Q[r1 * HIDDEN + c + 4] : 0u;
        }

        float o[4][4] = {};
        float l0 = 0.f, l1 = 0.f;

        uint4 kf0, kf1, vf0, vf1;
        if (tb < te) {
            int row = start + tb * 32 + lj;
            uint4 z = make_uint4(0u, 0u, 0u, 0u);
            kf0 = kf1 = vf0 = vf1 = z;
            if (row < end) {
                const uint4* kp = (const uint4*)&K[row * HIDDEN + kvoff];
                kf0 = kp[0]; kf1 = kp[1];
                const uint4* vp = (const uint4*)&V[row * HIDDEN + kvoff];
                vf0 = vp[0]; vf1 = vp[1];
            }
        }

        int buf = 0;
        for (int tt = tb; tt < te; tt++) {
            const int t0 = start + tt * 32;
            {
                uint2* kd = &Kp[buf][lj][lb * 4];
                kd[0] = make_uint2(kf0.x, kf1.x);
                kd[1] = make_uint2(kf0.y, kf1.y);
                kd[2] = make_uint2(kf0.z, kf1.z);
                kd[3] = make_uint2(kf0.w, kf1.w);
                *(uint4*)&Vs[buf][lj * 40 + lb * 8]     = vf0;
                *(uint4*)&Vs[buf][lj * 40 + lb * 8 + 4] = vf1;
            }
            if (tt + 1 < te) {
                int row = t0 + 32 + lj;
                uint4 z = make_uint4(0u, 0u, 0u, 0u);
                kf0 = kf1 = vf0 = vf1 = z;
                if (row < end) {
                    const uint4* kp = (const uint4*)&K[row * HIDDEN + kvoff];
                    kf0 = kp[0]; kf1 = kp[1];
                    const uint4* vp = (const uint4*)&V[row * HIDDEN + kvoff];
                    vf0 = vp[0]; vf1 = vp[1];
                }
            }
            __syncthreads();

            // ---- S = Q K^T (Q pre-scaled by QSCALE) ----
            float s[4][4] = {};
            #pragma unroll
            for (int fn = 0; fn < 4; fn++) {
                #pragma unroll
                for (int kk = 0; kk < 4; kk++) {
                    uint2 kb = Kp[buf][fn * 8 + gq][kk * 4 + tq];
                    uint32_t b2[2] = {kb.x, kb.y};
                    mma_tf32(s[fn], qa[kk], b2);
                }
            }

            // ---- mask (tail tile only) ----
            int tn = end - t0;
            if (tn < 32) {
                #pragma unroll
                for (int fn = 0; fn < 4; fn++) {
                    int c = fn * 8 + 2 * tq;
                    if (c >= tn)     { s[fn][0] = -1e30f; s[fn][2] = -1e30f; }
                    if (c + 1 >= tn) { s[fn][1] = -1e30f; s[fn][3] = -1e30f; }
                }
            }

            // ---- p = exp2(s); accumulate l; stage paired tf32 ----
            {
                uint32_t* prow0 = &Pw[wid][gq * 40];
                uint32_t* prow1 = &Pw[wid][(gq + 8) * 40];
                int w0b = ((2 * tq) & 3) * 2 + (tq >> 1);
                #pragma unroll
                for (int fn = 0; fn < 4; fn++) {
                    float p0 = exp2f(s[fn][0]), p1 = exp2f(s[fn][1]);
                    float p2 = exp2f(s[fn][2]), p3 = exp2f(s[fn][3]);
                    l0 += p0 + p1; l1 += p2 + p3;
                    int w0 = fn * 8 + w0b;
                    prow0[w0] = f2tf(p0); prow0[w0 + 2] = f2tf(p1);
                    prow1[w0] = f2tf(p2); prow1[w0 + 2] = f2tf(p3);
                }
            }
            __syncwarp();

            // ---- O += P V ----
            #pragma unroll
            for (int kk = 0; kk < 4; kk++) {
                uint2 a0 = *(const uint2*)&Pw[wid][gq * 40 + (kk * 4 + tq) * 2];
                uint2 a1 = *(const uint2*)&Pw[wid][(gq + 8) * 40 + (kk * 4 + tq) * 2];
                uint32_t pa[4] = {a0.x, a1.x, a0.y, a1.y};
                #pragma unroll
                for (int fn = 0; fn < 4; fn++) {
                    uint32_t b2[2] = { Vs[buf][(kk * 8 + tq) * 40 + fn * 8 + gq],
                                       Vs[buf][(kk * 8 + tq + 4) * 40 + fn * 8 + gq] };
                    mma_tf32(o[fn], pa, b2);
                }
            }
            buf ^= 1;
        }

        // ---- store partial l (per row) and partial o (fp32, unnormalized) ----
        l0 += __shfl_xor_sync(0xffffffffu, l0, 1);
        l0 += __shfl_xor_sync(0xffffffffu, l0, 2);
        l1 += __shfl_xor_sync(0xffffffffu, l1, 1);
        l1 += __shfl_xor_sync(0xffffffffu, l1, 2);
        if (tq == 0) {
            if (v0) LA[r0 * HEADS + hh] = l0;
            if (v1) LA[r1 * HEADS + hh] = l1;
        }
        #pragma unroll
        for (int fn = 0; fn < 4; fn++) {
            int col = hh * HEAD_DIM + fn * 8 + 2 * tq;
            if (v0) *(float2*)&OA[r0 * HIDDEN + col] = make_float2(o[fn][0], o[fn][1]);
            if (v1) *(float2*)&OA[r1 * HIDDEN + col] = make_float2(o[fn][2], o[fn][3]);
        }
    }
}

// ---------------------------------------------------------------------------
extern "C" void kernel_launch(void* const* d_in, const int* in_sizes, int n_in,
                              void* d_out, int out_size) {
    const float* x     = (const float*)d_in[0];
    const int*   batch = (const int*)  d_in[1];
    const float* Wq    = (const float*)d_in[2];
    const float* bq    = (const float*)d_in[3];
    const float* Wk    = (const float*)d_in[4];
    const float* bk    = (const float*)d_in[5];
    const float* Wv    = (const float*)d_in[6];
    const float* bv    = (const float*)d_in[7];
    const float* Wo    = (const float*)d_in[8];
    const float* bo    = (const float*)d_in[9];
    const float* gamma = (const float*)d_in[10];
    const float* beta  = (const float*)d_in[11];
    float* out = (float*)d_out;

    int n = in_sizes[0] / HIDDEN;   // 4096

    float *pq, *pk, *pv;
    cudaGetSymbolAddress((void**)&pq, g_q);
    cudaGetSymbolAddress((void**)&pk, g_k);
    cudaGetSymbolAddress((void**)&pv, g_v);

    prep_kernel<<<1 + n / 8, 256>>>(batch, n, x);

    dim3 gqkv(HIDDEN / 64, n / 64, 3);
    gemm_qkv_kernel<<<gqkv, 128>>>(x, gamma, beta,
                                   Wq, bq, pq, Wk, bk, pk, Wv, bv, pv);

    attn_kernel<<<dim3(NGRAPH, HEADS, 8), 128>>>();

    dim3 go(HIDDEN / 64, n / 32, 1);
    gemm_o_kernel<<<go, 128>>>(Wo, bo, x, out);
}